// round 3
// baseline (speedup 1.0000x reference)
#include <cuda_runtime.h>

#define N 384
#define D 512
#define MARGIN 0.5f
#define EPS 1e-6f

#define NSLOT 32           // hierarchical reduction fan-in
#define PAD 32             // 32 x 4B = 128B: one L2 line per slot, no hash pairing

// All zero-initialized at module load; the winners reset them each launch so
// every graph replay starts clean.
__device__ float g_slot_acc[NSLOT * PAD];
__device__ int   g_slot_cnt[NSLOT * PAD];
__device__ int   g_final_cnt;

__global__ __launch_bounds__(N) void triplet_fused_kernel(
    const float* __restrict__ features,
    const int*   __restrict__ labels,
    const int*   __restrict__ levels,
    float*       __restrict__ out) {
    __shared__ int   s_lab[N];
    __shared__ int   s_lev[N];
    __shared__ float s_dist[N];   // only same-label entries written/read
    __shared__ int   s_same[N];   // compacted same-label indices
    __shared__ int   s_negl[N];   // compacted negative indices
    __shared__ int   s_nsame, s_nneg, s_npos;
    __shared__ float s_sum;

    const int i = blockIdx.x;
    const int t = threadIdx.x;

    if (t == 0) { s_nsame = 0; s_nneg = 0; s_npos = 0; s_sum = 0.0f; }
    s_lab[t] = labels[t];
    s_lev[t] = levels[t];
    __syncthreads();

    const int lab_i = s_lab[i];
    const int lev_i = s_lev[i];
    const bool same = (t != i) && (s_lab[t] == lab_i);
    if (same) {
        int p = atomicAdd(&s_nsame, 1);
        s_same[p] = t;
        if (s_lev[t] != lev_i) {
            int q = atomicAdd(&s_nneg, 1);
            s_negl[q] = t;
        } else {
            atomicAdd(&s_npos, 1);
        }
    }
    __syncthreads();

    // Distances: warp w handles compacted same-label entries w, w+12, ...
    const int wid  = t >> 5;
    const int lane = t & 31;
    const int nw   = blockDim.x >> 5;  // 12 warps
    const float4* __restrict__ fi = (const float4*)(features + i * D);
    const int nsame = s_nsame;
    for (int m = wid; m < nsame; m += nw) {
        const int j = s_same[m];
        const float4* __restrict__ fj = (const float4*)(features + j * D);
        float acc = 0.0f;
#pragma unroll
        for (int u = 0; u < 4; u++) {
            const int idx = u * 32 + lane;   // coalesced per warp
            float4 a = fi[idx];
            float4 b = fj[idx];
            float d0 = a.x - b.x + EPS;      // torch pairwise_distance eps
            float d1 = a.y - b.y + EPS;
            float d2 = a.z - b.z + EPS;
            float d3 = a.w - b.w + EPS;
            acc = fmaf(d0, d0, acc);
            acc = fmaf(d1, d1, acc);
            acc = fmaf(d2, d2, acc);
            acc = fmaf(d3, d3, acc);
        }
#pragma unroll
        for (int o = 16; o; o >>= 1) acc += __shfl_xor_sync(0xffffffffu, acc, o);
        if (lane == 0) s_dist[j] = sqrtf(acc);
    }
    __syncthreads();

    // Hinge: thread t (if positive for anchor i) loops over compacted negs.
    const bool is_pos = same && (s_lev[t] == lev_i);
    float acc = 0.0f;
    if (is_pos) {
        const float dij = s_dist[t];
        const int nn = s_nneg;
        for (int q = 0; q < nn; q++) {
            acc += fmaxf(dij - s_dist[s_negl[q]] + MARGIN, 0.0f);
        }
    }
    if (acc != 0.0f) atomicAdd(&s_sum, acc);
    __syncthreads();

    // Hierarchical finalize: 12-way contention per slot line, then 32-way on
    // one counter, then a single winner gathers + resets + writes out.
    if (t == 0) {
        float contrib = 0.0f;
        const long long cnt = (long long)s_npos * (long long)s_nneg;
        if (cnt > 0) contrib = s_sum / (float)cnt * (1.0f / (float)N);

        const int slot = i & (NSLOT - 1);
        atomicAdd(&g_slot_acc[slot * PAD], contrib);
        __threadfence();
        const int tk = atomicAdd(&g_slot_cnt[slot * PAD], 1);
        if (tk == (N / NSLOT) - 1) {          // slot winner (12 blocks/slot)
            g_slot_cnt[slot * PAD] = 0;       // visible by next launch boundary
            __threadfence();
            const int f = atomicAdd(&g_final_cnt, 1);
            if (f == NSLOT - 1) {             // global winner
                g_final_cnt = 0;
                float sum = 0.0f;
#pragma unroll
                for (int s2 = 0; s2 < NSLOT; s2++) {
                    // atomicExch: reads through L2 (coherent with the adds)
                    // and resets the slot for the next graph replay.
                    sum += atomicExch(&g_slot_acc[s2 * PAD], 0.0f);
                }
                out[0] = sum;
            }
        }
    }
}

extern "C" void kernel_launch(void* const* d_in, const int* in_sizes, int n_in,
                              void* d_out, int out_size) {
    const float* features = (const float*)d_in[0];
    const int*   labels   = (const int*)d_in[1];
    const int*   levels   = (const int*)d_in[2];
    float* out = (float*)d_out;

    triplet_fused_kernel<<<N, N>>>(features, labels, levels, out);
}